// round 7
// baseline (speedup 1.0000x reference)
#include <cuda_runtime.h>
#include <cuda_fp16.h>
#include <stdint.h>
#include <math.h>

#define NMAX 100000
#define EMAX 3200000
#define GMAX 128
#define H 32
#define NCHUNK 148

// Scratch (device globals; zero-initialized at load; self-cleaned every call)
__device__ int     g_deg[NMAX];
__device__ float   g_dinv[NMAX];
__device__ float   g_xs[NMAX];
__device__ float   g_agg[NMAX];
__device__ int     g_rowstart[NMAX + 1];
__device__ int     g_cursor[NMAX];
__device__ int     g_csr[EMAX];
__device__ __half2 g_hsA[NMAX * 16];   // 16 half2 per row = 32 features
__device__ __half2 g_hsB[NMAX * 16];
__device__ float   g_gsum[GMAX * H];
__device__ float   g_gcnt[GMAX];
__device__ int     g_csum[NCHUNK];
__device__ int     g_cbase[NCHUNK + 1];

// ---------------- CSR build ----------------

__global__ void k_count_v4(const int* __restrict__ dst, int e4) {
    int i = blockIdx.x * blockDim.x + threadIdx.x;
    if (i < e4) {
        int4 d = ((const int4*)dst)[i];
        atomicAdd(&g_deg[d.x], 1);
        atomicAdd(&g_deg[d.y], 1);
        atomicAdd(&g_deg[d.z], 1);
        atomicAdd(&g_deg[d.w], 1);
    }
}
__global__ void k_count_s(const int* __restrict__ dst, int e) {
    int i = blockIdx.x * blockDim.x + threadIdx.x;
    if (i < e) atomicAdd(&g_deg[dst[i]], 1);
}

__global__ void k_chunksum(int n, int ch) {
    int b = blockIdx.x;
    int c0 = b * ch, c1 = min(n, c0 + ch);
    int tid = threadIdx.x, lane = tid & 31;
    __shared__ int sS[8];
    int v = 0;
    for (int i = c0 + tid; i < c1; i += blockDim.x) v += g_deg[i];
#pragma unroll
    for (int o = 16; o > 0; o >>= 1) v += __shfl_xor_sync(0xffffffffu, v, o);
    if (lane == 0) sS[tid >> 5] = v;
    __syncthreads();
    if (tid == 0) {
        int w = 0;
        for (int t = 0; t < (int)(blockDim.x >> 5); t++) w += sS[t];
        g_csum[b] = w;
    }
}

__global__ void k_basescan(int n) {
    __shared__ int sS[NCHUNK];
    int tid = threadIdx.x;
    if (tid < NCHUNK) sS[tid] = g_csum[tid];
    __syncthreads();
    if (tid == 0) {
        int run = 0;
        for (int b = 0; b < NCHUNK; b++) { int t = sS[b]; sS[b] = run; run += t; }
        g_cbase[NCHUNK] = run;
        g_rowstart[n] = run;
    }
    __syncthreads();
    if (tid < NCHUNK) g_cbase[tid] = sS[tid];
}

__global__ void __launch_bounds__(1024) k_chunkscan(const float* __restrict__ x, int n, int ch) {
    __shared__ int sS[1024];
    __shared__ int sCarry;
    int b = blockIdx.x;
    int c0 = b * ch, c1 = min(n, c0 + ch);
    int tid = threadIdx.x;
    if (tid == 0) sCarry = g_cbase[b];
    __syncthreads();
    for (int base = c0; base < c1; base += 1024) {
        int i = base + tid;
        int v = (i < c1) ? g_deg[i] : 0;
        sS[tid] = v;
        __syncthreads();
        for (int o = 1; o < 1024; o <<= 1) {
            int t = 0;
            if (tid >= o) t = sS[tid - o];
            __syncthreads();
            if (tid >= o) sS[tid] += t;
            __syncthreads();
        }
        int carry = sCarry;
        int excl = carry + sS[tid] - v;
        if (i < c1) {
            g_rowstart[i] = excl;
            g_cursor[i]   = excl;
            float dinv = rsqrtf((float)(v + 1));
            g_dinv[i] = dinv;
            g_xs[i]   = dinv * x[i];
            g_deg[i]  = 0;                          // self-clean
        }
        __syncthreads();
        if (tid == 0) sCarry = carry + sS[1023];
        __syncthreads();
    }
}

// Scatter CSR + fused layer-1 scalar aggregation
__global__ void k_scatter_v4(const int* __restrict__ src, const int* __restrict__ dst, int e4) {
    int i = blockIdx.x * blockDim.x + threadIdx.x;
    if (i < e4) {
        int4 d = ((const int4*)dst)[i];
        int4 s = ((const int4*)src)[i];
        g_csr[atomicAdd(&g_cursor[d.x], 1)] = s.x;
        g_csr[atomicAdd(&g_cursor[d.y], 1)] = s.y;
        g_csr[atomicAdd(&g_cursor[d.z], 1)] = s.z;
        g_csr[atomicAdd(&g_cursor[d.w], 1)] = s.w;
        atomicAdd(&g_agg[d.x], __ldg(&g_xs[s.x]));
        atomicAdd(&g_agg[d.y], __ldg(&g_xs[s.y]));
        atomicAdd(&g_agg[d.z], __ldg(&g_xs[s.z]));
        atomicAdd(&g_agg[d.w], __ldg(&g_xs[s.w]));
    }
}
__global__ void k_scatter_s(const int* __restrict__ src, const int* __restrict__ dst, int e) {
    int i = blockIdx.x * blockDim.x + threadIdx.x;
    if (i < e) {
        int d = dst[i], s = src[i];
        g_csr[atomicAdd(&g_cursor[d], 1)] = s;
        atomicAdd(&g_agg[d], __ldg(&g_xs[s]));
    }
}

// Pack a per-lane float (lane = feature) into a half2 row in hs.
__device__ __forceinline__ void store_row_h(__half2* __restrict__ hs, int i, float val, int lane) {
    float nb = __shfl_down_sync(0xffffffffu, val, 1);
    if ((lane & 1) == 0)
        hs[i * 16 + (lane >> 1)] = __floats2half2_rn(val, nb);
}

// ---------------- Layer 1 (rank-1, no gather) + transform by W2 ----------------

__global__ void __launch_bounds__(256) k_l1(const float* __restrict__ W1, const float* __restrict__ b1,
                                            const float* __restrict__ W2, int n) {
    int tid  = threadIdx.x;
    int lane = tid & 31;
    int wg   = (blockIdx.x * blockDim.x + tid) >> 5;
    int nw   = (gridDim.x * blockDim.x) >> 5;
    float wc[H];
#pragma unroll
    for (int k = 0; k < H; k++) wc[k] = __ldg(&W2[k * H + lane]);
    float w1  = __ldg(&W1[lane]);
    float bb1 = __ldg(&b1[lane]);
    for (int i = wg; i < n; i += nw) {
        float dinv = g_dinv[i];
        float S = g_agg[i] + g_xs[i];
        if (lane == 0) g_agg[i] = 0.f;            // self-clean
        float x1 = fmaxf(dinv * S * w1 + bb1, 0.f);
        float acc = 0.f;
#pragma unroll
        for (int k = 0; k < H; k++)
            acc += __shfl_sync(0xffffffffu, x1, k) * wc[k];
        store_row_h(g_hsA, i, acc * dinv, lane);
    }
}

// ---------------- Half-row gather core ----------------
// lane = 4*g' layout: g = lane>>2 (edge subgroup 0..7), q = lane&3 (16B row quarter).
// Per 32 edges: 4 LDG.128, each fetching 8 rows' quarters. fp32 accumulation.
// Returns per-feature neighbor+self sum redistributed to lane=feature via smem xrow[32].
__device__ __forceinline__ float quad_gather_h(const __half2* __restrict__ hs,
                                               float* __restrict__ xrow,
                                               int i, int st, int en, int lane) {
    int q = lane & 3, g = lane >> 2;
    float a0 = 0.f, a1 = 0.f, a2 = 0.f, a3 = 0.f, a4 = 0.f, a5 = 0.f, a6 = 0.f, a7 = 0.f;
    int e = st;
    while (en - e >= 32) {
        int idx = __ldg(&g_csr[e + lane]);
#pragma unroll
        for (int t = 0; t < 4; t++) {
            int j = __shfl_sync(0xffffffffu, idx, t * 8 + g);
            int4 rw = *reinterpret_cast<const int4*>(&hs[j * 16 + q * 4]);
            float2 f0 = __half22float2(*reinterpret_cast<__half2*>(&rw.x));
            float2 f1 = __half22float2(*reinterpret_cast<__half2*>(&rw.y));
            float2 f2 = __half22float2(*reinterpret_cast<__half2*>(&rw.z));
            float2 f3 = __half22float2(*reinterpret_cast<__half2*>(&rw.w));
            a0 += f0.x; a1 += f0.y; a2 += f1.x; a3 += f1.y;
            a4 += f2.x; a5 += f2.y; a6 += f3.x; a7 += f3.y;
        }
        e += 32;
    }
    int m = en - e;
    if (m > 0) {
        int idx = (lane < m) ? __ldg(&g_csr[e + lane]) : 0;
        int nt = (m + 7) >> 3;
        for (int t = 0; t < nt; t++) {
            int ei = t * 8 + g;
            int j = __shfl_sync(0xffffffffu, idx, ei & 31);
            if (ei < m) {
                int4 rw = *reinterpret_cast<const int4*>(&hs[j * 16 + q * 4]);
                float2 f0 = __half22float2(*reinterpret_cast<__half2*>(&rw.x));
                float2 f1 = __half22float2(*reinterpret_cast<__half2*>(&rw.y));
                float2 f2 = __half22float2(*reinterpret_cast<__half2*>(&rw.z));
                float2 f3 = __half22float2(*reinterpret_cast<__half2*>(&rw.w));
                a0 += f0.x; a1 += f0.y; a2 += f1.x; a3 += f1.y;
                a4 += f2.x; a5 += f2.y; a6 += f3.x; a7 += f3.y;
            }
        }
    }
    // reduce across the 8 edge subgroups (lanes q, q+4, ..., q+28)
#pragma unroll
    for (int o = 4; o <= 16; o <<= 1) {
        a0 += __shfl_xor_sync(0xffffffffu, a0, o);
        a1 += __shfl_xor_sync(0xffffffffu, a1, o);
        a2 += __shfl_xor_sync(0xffffffffu, a2, o);
        a3 += __shfl_xor_sync(0xffffffffu, a3, o);
        a4 += __shfl_xor_sync(0xffffffffu, a4, o);
        a5 += __shfl_xor_sync(0xffffffffu, a5, o);
        a6 += __shfl_xor_sync(0xffffffffu, a6, o);
        a7 += __shfl_xor_sync(0xffffffffu, a7, o);
    }
    // self term
    {
        int4 rw = *reinterpret_cast<const int4*>(&hs[i * 16 + q * 4]);
        float2 f0 = __half22float2(*reinterpret_cast<__half2*>(&rw.x));
        float2 f1 = __half22float2(*reinterpret_cast<__half2*>(&rw.y));
        float2 f2 = __half22float2(*reinterpret_cast<__half2*>(&rw.z));
        float2 f3 = __half22float2(*reinterpret_cast<__half2*>(&rw.w));
        a0 += f0.x; a1 += f0.y; a2 += f1.x; a3 += f1.y;
        a4 += f2.x; a5 += f2.y; a6 += f3.x; a7 += f3.y;
    }
    if (g == 0) {
        float* xq = &xrow[q * 8];
        xq[0] = a0; xq[1] = a1; xq[2] = a2; xq[3] = a3;
        xq[4] = a4; xq[5] = a5; xq[6] = a6; xq[7] = a7;
    }
    __syncwarp();
    float r = xrow[lane];
    __syncwarp();
    return r;
}

// ---------------- Layer 2 gather + transform by W3 ----------------

__global__ void __launch_bounds__(256) k_g2(const float* __restrict__ b2, const float* __restrict__ W3, int n) {
    __shared__ float Xr[8][H];
    int tid  = threadIdx.x;
    int lane = tid & 31;
    int wg   = (blockIdx.x * blockDim.x + tid) >> 5;
    int nw   = (gridDim.x * blockDim.x) >> 5;
    float wc[H];
#pragma unroll
    for (int k = 0; k < H; k++) wc[k] = __ldg(&W3[k * H + lane]);
    float bb2 = __ldg(&b2[lane]);
    float* xr = Xr[tid >> 5];
    for (int i = wg; i < n; i += nw) {
        float dinv = g_dinv[i];
        int st = g_rowstart[i], en = g_rowstart[i + 1];
        float s = quad_gather_h(g_hsA, xr, i, st, en, lane);
        float x2 = fmaxf(s * dinv + bb2, 0.f);
        float acc = 0.f;
#pragma unroll
        for (int k = 0; k < H; k++)
            acc += __shfl_sync(0xffffffffu, x2, k) * wc[k];
        store_row_h(g_hsB, i, acc * dinv, lane);
    }
}

// ---------------- Layer 3 gather + theta head + pooling ----------------

__global__ void __launch_bounds__(256) k_g3(const float* __restrict__ b3, const int* __restrict__ batch,
                                            const float* __restrict__ Wt1, const float* __restrict__ bt1,
                                            const float* __restrict__ Wt2, const float* __restrict__ bt2,
                                            float* __restrict__ out, int n) {
    __shared__ float Xr[8][H];
    int tid  = threadIdx.x;
    int lane = tid & 31;
    int wg   = (blockIdx.x * blockDim.x + tid) >> 5;
    int nw   = (gridDim.x * blockDim.x) >> 5;
    float wc[H];
#pragma unroll
    for (int k = 0; k < H; k++) wc[k] = __ldg(&Wt1[k * H + lane]);
    float bb3  = __ldg(&b3[lane]);
    float bt1l = __ldg(&bt1[lane]);
    float wt2l = __ldg(&Wt2[lane]);
    float bt2s = __ldg(&bt2[0]);
    float* xr = Xr[tid >> 5];
    for (int i = wg; i < n; i += nw) {
        float dinv = g_dinv[i];
        int st = g_rowstart[i], en = g_rowstart[i + 1];
        float s = quad_gather_h(g_hsB, xr, i, st, en, lane);
        float h = fmaxf(s * dinv + bb3, 0.f);
        float acc = bt1l;
#pragma unroll
        for (int k = 0; k < H; k++)
            acc += __shfl_sync(0xffffffffu, h, k) * wc[k];
        float p = fmaxf(acc, 0.f) * wt2l;
#pragma unroll
        for (int o = 16; o > 0; o >>= 1) p += __shfl_xor_sync(0xffffffffu, p, o);
        int g = batch[i];
        atomicAdd(&g_gsum[g * H + lane], h);
        if (lane == 0) {
            atomicAdd(&g_gcnt[g], 1.f);
            out[i] = 3.14159265358979323846f / (1.f + expf(-(p + bt2s)));
        }
    }
}

// ---------------- Per-graph MLP head (+ self-clean) ----------------

__global__ void k_graph(const float* __restrict__ Wg1, const float* __restrict__ bg1,
                        const float* __restrict__ Wg2, const float* __restrict__ bg2,
                        float* __restrict__ out, int n, int g) {
    int wid = (blockIdx.x * blockDim.x + threadIdx.x) >> 5;
    int lane = threadIdx.x & 31;
    if (wid >= g) return;
    float cnt = g_gcnt[wid];
    float ge = g_gsum[wid * H + lane] / fmaxf(cnt, 1.f);
    g_gsum[wid * H + lane] = 0.f;                  // self-clean
    if (lane == 0) g_gcnt[wid] = 0.f;
    float acc = __ldg(&bg1[lane]);
#pragma unroll
    for (int k = 0; k < H; k++)
        acc += __shfl_sync(0xffffffffu, ge, k) * __ldg(&Wg1[k * H + lane]);
    float t = fmaxf(acc, 0.f);
    float p0 = t * __ldg(&Wg2[lane * 2 + 0]);
    float p1 = t * __ldg(&Wg2[lane * 2 + 1]);
#pragma unroll
    for (int o = 16; o > 0; o >>= 1) {
        p0 += __shfl_xor_sync(0xffffffffu, p0, o);
        p1 += __shfl_xor_sync(0xffffffffu, p1, o);
    }
    if (lane == 0) {
        const float TWO_PI = 6.28318530717958647692f;
        out[n + wid * 2 + 0] = TWO_PI / (1.f + expf(-(p0 + __ldg(&bg2[0]))));
        out[n + wid * 2 + 1] = TWO_PI / (1.f + expf(-(p1 + __ldg(&bg2[1]))));
    }
}

extern "C" void kernel_launch(void* const* d_in, const int* in_sizes, int n_in,
                              void* d_out, int out_size) {
    const float* x   = (const float*)d_in[0];
    const int*   ei  = (const int*)d_in[1];
    const int*   bat = (const int*)d_in[2];
    const float* W1  = (const float*)d_in[3];
    const float* b1  = (const float*)d_in[4];
    const float* W2  = (const float*)d_in[5];
    const float* b2  = (const float*)d_in[6];
    const float* W3  = (const float*)d_in[7];
    const float* b3  = (const float*)d_in[8];
    const float* Wt1 = (const float*)d_in[9];
    const float* bt1 = (const float*)d_in[10];
    const float* Wt2 = (const float*)d_in[11];
    const float* bt2 = (const float*)d_in[12];
    const float* Wg1 = (const float*)d_in[13];
    const float* bg1 = (const float*)d_in[14];
    const float* Wg2 = (const float*)d_in[15];
    const float* bg2 = (const float*)d_in[16];
    float* out = (float*)d_out;

    int N = in_sizes[0];
    int E = in_sizes[1] / 2;
    int G = (out_size - N) / 2;

    const int* src = ei;
    const int* dst = ei + E;

    const int TB = 256;
    int CH = (N + NCHUNK - 1) / NCHUNK;
    int nb_g = (G * 32 + TB - 1) / TB;

    bool vec4 = ((E & 3) == 0) &&
                ((((unsigned long long)src) & 15ull) == 0) &&
                ((((unsigned long long)dst) & 15ull) == 0);

    if (vec4) {
        int e4 = E / 4;
        int nb = (e4 + TB - 1) / TB;
        k_count_v4<<<nb, TB>>>(dst, e4);
        k_chunksum<<<NCHUNK, TB>>>(N, CH);
        k_basescan<<<1, 256>>>(N);
        k_chunkscan<<<NCHUNK, 1024>>>(x, N, CH);
        k_scatter_v4<<<nb, TB>>>(src, dst, e4);
    } else {
        int nb = (E + TB - 1) / TB;
        k_count_s<<<nb, TB>>>(dst, E);
        k_chunksum<<<NCHUNK, TB>>>(N, CH);
        k_basescan<<<1, 256>>>(N);
        k_chunkscan<<<NCHUNK, 1024>>>(x, N, CH);
        k_scatter_s<<<nb, TB>>>(src, dst, E);
    }

    k_l1<<<296, TB>>>(W1, b1, W2, N);
    k_g2<<<592, TB>>>(b2, W3, N);
    k_g3<<<592, TB>>>(b3, bat, Wt1, bt1, Wt2, bt2, out, N);
    k_graph<<<nb_g, TB>>>(Wg1, bg1, Wg2, bg2, out, N, G);
}

// round 8
// speedup vs baseline: 1.0943x; 1.0943x over previous
#include <cuda_runtime.h>
#include <stdint.h>
#include <math.h>

#define NMAX 100000
#define EMAX 3200000
#define GMAX 128
#define H 32
#define NCHUNK 128
#define CH 784            // nodes per chunk (128*784 = 100352 >= 100000)
#define SLICE 98          // nodes per sumscan thread (1024*98 = 100352)

// Scratch (device globals; zero-initialized at load; self-cleaned every call)
__device__ int   g_deg[NMAX];
__device__ float g_dinv[NMAX];
__device__ float g_xs[NMAX];
__device__ float g_agg[NMAX];
__device__ int   g_rowstart[NMAX + 1];
__device__ int   g_cursor[NMAX];
__device__ int   g_csr[EMAX];
__device__ float g_hsA[NMAX * H];
__device__ float g_hsB[NMAX * H];
__device__ float g_gsum[GMAX * H];
__device__ float g_gcnt[GMAX];
__device__ int   g_cbase[NCHUNK + 1];

// ---------------- CSR build ----------------

__global__ void k_count_v4(const int* __restrict__ dst, int e4) {
    int i = blockIdx.x * blockDim.x + threadIdx.x;
    if (i < e4) {
        int4 d = ((const int4*)dst)[i];
        atomicAdd(&g_deg[d.x], 1);
        atomicAdd(&g_deg[d.y], 1);
        atomicAdd(&g_deg[d.z], 1);
        atomicAdd(&g_deg[d.w], 1);
    }
}
__global__ void k_count_s(const int* __restrict__ dst, int e) {
    int i = blockIdx.x * blockDim.x + threadIdx.x;
    if (i < e) atomicAdd(&g_deg[dst[i]], 1);
}

// One block: per-thread slice sums -> block scan -> chunk bases.
__global__ void __launch_bounds__(1024) k_sumscan(int n) {
    __shared__ int sS[1024];
    int t = threadIdx.x;
    int s0 = t * SLICE, s1 = min(n, s0 + SLICE);
    int v = 0;
    for (int i = s0; i < s1; i++) v += g_deg[i];
    sS[t] = v;
    __syncthreads();
    for (int o = 1; o < 1024; o <<= 1) {
        int u = (t >= o) ? sS[t - o] : 0;
        __syncthreads();
        sS[t] += u;
        __syncthreads();
    }
    int incl = sS[t];
    if ((t & 7) == 0) g_cbase[t >> 3] = incl - v;   // 8 slices per chunk
    if (t == 1023) { g_cbase[NCHUNK] = incl; g_rowstart[n] = incl; }
}

// Per-chunk scan (single pass, CH <= 1024) -> rowstart/cursor/dinv/xs; zero deg.
__global__ void __launch_bounds__(1024) k_chunkscan(const float* __restrict__ x, int n) {
    __shared__ int sS[1024];
    int b = blockIdx.x;
    int c0 = b * CH;
    int tid = threadIdx.x;
    int i = c0 + tid;
    int v = (tid < CH && i < n) ? g_deg[i] : 0;
    sS[tid] = v;
    __syncthreads();
    for (int o = 1; o < 1024; o <<= 1) {
        int u = (tid >= o) ? sS[tid - o] : 0;
        __syncthreads();
        sS[tid] += u;
        __syncthreads();
    }
    int excl = g_cbase[b] + sS[tid] - v;
    if (tid < CH && i < n) {
        g_rowstart[i] = excl;
        g_cursor[i]   = excl;
        float dinv = rsqrtf((float)(v + 1));
        g_dinv[i] = dinv;
        g_xs[i]   = dinv * x[i];
        g_deg[i]  = 0;                              // self-clean
    }
}

// Scatter CSR + fused layer-1 scalar aggregation
__global__ void k_scatter_v4(const int* __restrict__ src, const int* __restrict__ dst, int e4) {
    int i = blockIdx.x * blockDim.x + threadIdx.x;
    if (i < e4) {
        int4 d = ((const int4*)dst)[i];
        int4 s = ((const int4*)src)[i];
        g_csr[atomicAdd(&g_cursor[d.x], 1)] = s.x;
        g_csr[atomicAdd(&g_cursor[d.y], 1)] = s.y;
        g_csr[atomicAdd(&g_cursor[d.z], 1)] = s.z;
        g_csr[atomicAdd(&g_cursor[d.w], 1)] = s.w;
        atomicAdd(&g_agg[d.x], __ldg(&g_xs[s.x]));
        atomicAdd(&g_agg[d.y], __ldg(&g_xs[s.y]));
        atomicAdd(&g_agg[d.z], __ldg(&g_xs[s.z]));
        atomicAdd(&g_agg[d.w], __ldg(&g_xs[s.w]));
    }
}
__global__ void k_scatter_s(const int* __restrict__ src, const int* __restrict__ dst, int e) {
    int i = blockIdx.x * blockDim.x + threadIdx.x;
    if (i < e) {
        int d = dst[i], s = src[i];
        g_csr[atomicAdd(&g_cursor[d], 1)] = s;
        atomicAdd(&g_agg[d], __ldg(&g_xs[s]));
    }
}

// ---------------- Layer 1 (rank-1, no gather) + transform by W2 ----------------

__global__ void __launch_bounds__(256) k_l1(const float* __restrict__ W1, const float* __restrict__ b1,
                                            const float* __restrict__ W2, int n) {
    int tid  = threadIdx.x;
    int lane = tid & 31;
    int wg   = (blockIdx.x * blockDim.x + tid) >> 5;
    int nw   = (gridDim.x * blockDim.x) >> 5;
    float wc[H];
#pragma unroll
    for (int k = 0; k < H; k++) wc[k] = __ldg(&W2[k * H + lane]);
    float w1  = __ldg(&W1[lane]);
    float bb1 = __ldg(&b1[lane]);
    for (int i = wg; i < n; i += nw) {
        float dinv = g_dinv[i];
        float S = g_agg[i] + g_xs[i];
        if (lane == 0) g_agg[i] = 0.f;            // self-clean
        float x1 = fmaxf(dinv * S * w1 + bb1, 0.f);
        float acc = 0.f;
#pragma unroll
        for (int k = 0; k < H; k++)
            acc += __shfl_sync(0xffffffffu, x1, k) * wc[k];
        g_hsA[i * H + lane] = acc * dinv;
    }
}

// ---------------- Pipelined quad-edge float4 gather ----------------
// lane = 8*g + q (g = edge subgroup 0..3, q = feature quad 0..7).
// csr indices for block k+1 are prefetched while block k's rows load.
__device__ __forceinline__ float quad_gather(const float* __restrict__ hs,
                                             float* __restrict__ xrow,
                                             int i, int st, int en, int lane) {
    int q = lane & 7, g = lane >> 3;
    float4 a = make_float4(0.f, 0.f, 0.f, 0.f);
    int nfull = (en - st) >> 5;
    int e = st;
    int idx = 0;
    if (st + lane < en) idx = __ldg(&g_csr[st + lane]);
    for (int blk = 0; blk < nfull; blk++) {
        int nidx = 0;
        int pe = e + 32 + lane;
        if (pe < en) nidx = __ldg(&g_csr[pe]);        // prefetch next block / remainder
#pragma unroll
        for (int t = 0; t < 8; t++) {
            int j = __shfl_sync(0xffffffffu, idx, t * 4 + g);
            const float4 v = *reinterpret_cast<const float4*>(&hs[j * H + q * 4]);
            a.x += v.x; a.y += v.y; a.z += v.z; a.w += v.w;
        }
        idx = nidx;
        e += 32;
    }
    int m = en - e;
    if (m > 0) {
        int nt = (m + 3) >> 2;
        for (int t = 0; t < nt; t++) {
            int ei = t * 4 + g;
            int j = __shfl_sync(0xffffffffu, idx, ei & 31);
            if (ei < m) {
                const float4 v = *reinterpret_cast<const float4*>(&hs[j * H + q * 4]);
                a.x += v.x; a.y += v.y; a.z += v.z; a.w += v.w;
            }
        }
    }
#pragma unroll
    for (int o = 8; o <= 16; o <<= 1) {
        a.x += __shfl_xor_sync(0xffffffffu, a.x, o);
        a.y += __shfl_xor_sync(0xffffffffu, a.y, o);
        a.z += __shfl_xor_sync(0xffffffffu, a.z, o);
        a.w += __shfl_xor_sync(0xffffffffu, a.w, o);
    }
    const float4 sv = *reinterpret_cast<const float4*>(&hs[i * H + q * 4]);
    a.x += sv.x; a.y += sv.y; a.z += sv.z; a.w += sv.w;
    if (g == 0) *reinterpret_cast<float4*>(&xrow[q * 4]) = a;
    __syncwarp();
    float r = xrow[lane];
    __syncwarp();
    return r;
}

// ---------------- Layer 2 gather + transform by W3 ----------------

__global__ void __launch_bounds__(256) k_g2(const float* __restrict__ b2, const float* __restrict__ W3, int n) {
    __shared__ float Xr[8][H];
    int tid  = threadIdx.x;
    int lane = tid & 31;
    int wg   = (blockIdx.x * blockDim.x + tid) >> 5;
    int nw   = (gridDim.x * blockDim.x) >> 5;
    float wc[H];
#pragma unroll
    for (int k = 0; k < H; k++) wc[k] = __ldg(&W3[k * H + lane]);
    float bb2 = __ldg(&b2[lane]);
    float* xr = Xr[tid >> 5];
    if (wg >= n) return;
    int st = g_rowstart[wg], en = g_rowstart[wg + 1];
    float dinv = g_dinv[wg];
    for (int i = wg; i < n; i += nw) {
        int inext = i + nw;
        int stn = 0, enn = 0; float dinvn = 0.f;
        if (inext < n) {                              // prefetch next node's metadata
            stn = __ldg(&g_rowstart[inext]);
            enn = __ldg(&g_rowstart[inext + 1]);
            dinvn = __ldg(&g_dinv[inext]);
        }
        float s = quad_gather(g_hsA, xr, i, st, en, lane);
        float x2 = fmaxf(s * dinv + bb2, 0.f);
        float acc = 0.f;
#pragma unroll
        for (int k = 0; k < H; k++)
            acc += __shfl_sync(0xffffffffu, x2, k) * wc[k];
        g_hsB[i * H + lane] = acc * dinv;
        st = stn; en = enn; dinv = dinvn;
    }
}

// ---------------- Layer 3 gather + theta head + pooling ----------------

__global__ void __launch_bounds__(256) k_g3(const float* __restrict__ b3, const int* __restrict__ batch,
                                            const float* __restrict__ Wt1, const float* __restrict__ bt1,
                                            const float* __restrict__ Wt2, const float* __restrict__ bt2,
                                            float* __restrict__ out, int n) {
    __shared__ float Xr[8][H];
    int tid  = threadIdx.x;
    int lane = tid & 31;
    int wg   = (blockIdx.x * blockDim.x + tid) >> 5;
    int nw   = (gridDim.x * blockDim.x) >> 5;
    float wc[H];
#pragma unroll
    for (int k = 0; k < H; k++) wc[k] = __ldg(&Wt1[k * H + lane]);
    float bb3  = __ldg(&b3[lane]);
    float bt1l = __ldg(&bt1[lane]);
    float wt2l = __ldg(&Wt2[lane]);
    float bt2s = __ldg(&bt2[0]);
    float* xr = Xr[tid >> 5];
    if (wg >= n) return;
    int st = g_rowstart[wg], en = g_rowstart[wg + 1];
    float dinv = g_dinv[wg];
    for (int i = wg; i < n; i += nw) {
        int inext = i + nw;
        int stn = 0, enn = 0; float dinvn = 0.f;
        if (inext < n) {
            stn = __ldg(&g_rowstart[inext]);
            enn = __ldg(&g_rowstart[inext + 1]);
            dinvn = __ldg(&g_dinv[inext]);
        }
        float s = quad_gather(g_hsB, xr, i, st, en, lane);
        float h = fmaxf(s * dinv + bb3, 0.f);
        float acc = bt1l;
#pragma unroll
        for (int k = 0; k < H; k++)
            acc += __shfl_sync(0xffffffffu, h, k) * wc[k];
        float p = fmaxf(acc, 0.f) * wt2l;
#pragma unroll
        for (int o = 16; o > 0; o >>= 1) p += __shfl_xor_sync(0xffffffffu, p, o);
        int g = batch[i];
        atomicAdd(&g_gsum[g * H + lane], h);
        if (lane == 0) {
            atomicAdd(&g_gcnt[g], 1.f);
            out[i] = 3.14159265358979323846f / (1.f + expf(-(p + bt2s)));
        }
        st = stn; en = enn; dinv = dinvn;
    }
}

// ---------------- Per-graph MLP head (+ self-clean) ----------------

__global__ void k_graph(const float* __restrict__ Wg1, const float* __restrict__ bg1,
                        const float* __restrict__ Wg2, const float* __restrict__ bg2,
                        float* __restrict__ out, int n, int g) {
    int wid = (blockIdx.x * blockDim.x + threadIdx.x) >> 5;
    int lane = threadIdx.x & 31;
    if (wid >= g) return;
    float cnt = g_gcnt[wid];
    float ge = g_gsum[wid * H + lane] / fmaxf(cnt, 1.f);
    g_gsum[wid * H + lane] = 0.f;                  // self-clean
    if (lane == 0) g_gcnt[wid] = 0.f;
    float acc = __ldg(&bg1[lane]);
#pragma unroll
    for (int k = 0; k < H; k++)
        acc += __shfl_sync(0xffffffffu, ge, k) * __ldg(&Wg1[k * H + lane]);
    float t = fmaxf(acc, 0.f);
    float p0 = t * __ldg(&Wg2[lane * 2 + 0]);
    float p1 = t * __ldg(&Wg2[lane * 2 + 1]);
#pragma unroll
    for (int o = 16; o > 0; o >>= 1) {
        p0 += __shfl_xor_sync(0xffffffffu, p0, o);
        p1 += __shfl_xor_sync(0xffffffffu, p1, o);
    }
    if (lane == 0) {
        const float TWO_PI = 6.28318530717958647692f;
        out[n + wid * 2 + 0] = TWO_PI / (1.f + expf(-(p0 + __ldg(&bg2[0]))));
        out[n + wid * 2 + 1] = TWO_PI / (1.f + expf(-(p1 + __ldg(&bg2[1]))));
    }
}

extern "C" void kernel_launch(void* const* d_in, const int* in_sizes, int n_in,
                              void* d_out, int out_size) {
    const float* x   = (const float*)d_in[0];
    const int*   ei  = (const int*)d_in[1];
    const int*   bat = (const int*)d_in[2];
    const float* W1  = (const float*)d_in[3];
    const float* b1  = (const float*)d_in[4];
    const float* W2  = (const float*)d_in[5];
    const float* b2  = (const float*)d_in[6];
    const float* W3  = (const float*)d_in[7];
    const float* b3  = (const float*)d_in[8];
    const float* Wt1 = (const float*)d_in[9];
    const float* bt1 = (const float*)d_in[10];
    const float* Wt2 = (const float*)d_in[11];
    const float* bt2 = (const float*)d_in[12];
    const float* Wg1 = (const float*)d_in[13];
    const float* bg1 = (const float*)d_in[14];
    const float* Wg2 = (const float*)d_in[15];
    const float* bg2 = (const float*)d_in[16];
    float* out = (float*)d_out;

    int N = in_sizes[0];
    int E = in_sizes[1] / 2;
    int G = (out_size - N) / 2;

    const int* src = ei;
    const int* dst = ei + E;

    const int TB = 256;
    int nb_g = (G * 32 + TB - 1) / TB;

    bool vec4 = ((E & 3) == 0) &&
                ((((unsigned long long)src) & 15ull) == 0) &&
                ((((unsigned long long)dst) & 15ull) == 0);

    if (vec4) {
        int e4 = E / 4;
        int nb = (e4 + TB - 1) / TB;
        k_count_v4<<<nb, TB>>>(dst, e4);
        k_sumscan<<<1, 1024>>>(N);
        k_chunkscan<<<NCHUNK, 1024>>>(x, N);
        k_scatter_v4<<<nb, TB>>>(src, dst, e4);    // launch index 3 -> profiled
    } else {
        int nb = (E + TB - 1) / TB;
        k_count_s<<<nb, TB>>>(dst, E);
        k_sumscan<<<1, 1024>>>(N);
        k_chunkscan<<<NCHUNK, 1024>>>(x, N);
        k_scatter_s<<<nb, TB>>>(src, dst, E);
    }

    k_l1<<<296, TB>>>(W1, b1, W2, N);
    k_g2<<<592, TB>>>(b2, W3, N);
    k_g3<<<592, TB>>>(b3, bat, Wt1, bt1, Wt2, bt2, out, N);
    k_graph<<<nb_g, TB>>>(Wg1, bg1, Wg2, bg2, out, N, G);
}

// round 9
// speedup vs baseline: 1.3328x; 1.2180x over previous
#include <cuda_runtime.h>
#include <stdint.h>
#include <math.h>

#define NMAX 100000
#define EMAX 3200000
#define GMAX 128
#define H 32
#define NCHUNK 128

// Scratch (device globals; zero-initialized at load; self-cleaned every call)
__device__ int   g_deg[NMAX];
__device__ float g_dinv[NMAX];
__device__ float g_xs[NMAX];
__device__ float g_agg[NMAX];
__device__ int   g_rowstart[NMAX + 1];
__device__ int   g_cursor[NMAX];
__device__ int   g_csr[EMAX];
__device__ float g_hsA[NMAX * H];
__device__ float g_hsB[NMAX * H];
__device__ float g_gsum[GMAX * H];
__device__ float g_gcnt[GMAX];
__device__ int   g_csum[NCHUNK];

// ---------------- CSR build ----------------

__global__ void k_count_v4(const int* __restrict__ dst, int e4) {
    int i = blockIdx.x * blockDim.x + threadIdx.x;
    if (i < e4) {
        int4 d = ((const int4*)dst)[i];
        atomicAdd(&g_deg[d.x], 1);
        atomicAdd(&g_deg[d.y], 1);
        atomicAdd(&g_deg[d.z], 1);
        atomicAdd(&g_deg[d.w], 1);
    }
}
__global__ void k_count_s(const int* __restrict__ dst, int e) {
    int i = blockIdx.x * blockDim.x + threadIdx.x;
    if (i < e) atomicAdd(&g_deg[dst[i]], 1);
}

// Per-chunk degree sums; 128 blocks, coalesced strided reads.
__global__ void k_chunksum(int n, int ch) {
    int b = blockIdx.x;
    int c0 = b * ch, c1 = min(n, c0 + ch);
    int tid = threadIdx.x, lane = tid & 31;
    __shared__ int sS[8];
    int v = 0;
    for (int i = c0 + tid; i < c1; i += blockDim.x) v += g_deg[i];
#pragma unroll
    for (int o = 16; o > 0; o >>= 1) v += __shfl_xor_sync(0xffffffffu, v, o);
    if (lane == 0) sS[tid >> 5] = v;
    __syncthreads();
    if (tid == 0) {
        int w = 0;
        for (int t = 0; t < (int)(blockDim.x >> 5); t++) w += sS[t];
        g_csum[b] = w;
    }
}

// Per-chunk scan (single pass, ch <= 1024). Each block also scans the 128
// chunk sums in smem to get its base (folds the old basescan launch in).
__global__ void __launch_bounds__(1024) k_chunkscan(const float* __restrict__ x, int n, int ch) {
    __shared__ int sS[1024];
    __shared__ int sBase[NCHUNK + 1];
    int b = blockIdx.x;
    int tid = threadIdx.x;
    if (tid < NCHUNK) sBase[tid] = g_csum[tid];
    __syncthreads();
    if (tid == 0) {
        int run = 0;
        for (int c = 0; c < NCHUNK; c++) { int t = sBase[c]; sBase[c] = run; run += t; }
        sBase[NCHUNK] = run;
    }
    __syncthreads();
    int c0 = b * ch;
    int i = c0 + tid;
    int v = (tid < ch && i < n) ? g_deg[i] : 0;
    sS[tid] = v;
    __syncthreads();
    for (int o = 1; o < 1024; o <<= 1) {
        int u = (tid >= o) ? sS[tid - o] : 0;
        __syncthreads();
        sS[tid] += u;
        __syncthreads();
    }
    int excl = sBase[b] + sS[tid] - v;
    if (tid < ch && i < n) {
        g_rowstart[i] = excl;
        g_cursor[i]   = excl;
        float dinv = rsqrtf((float)(v + 1));
        g_dinv[i] = dinv;
        g_xs[i]   = dinv * x[i];
        g_deg[i]  = 0;                              // self-clean
    }
    if (b == NCHUNK - 1 && tid == 0) g_rowstart[n] = sBase[NCHUNK];
}

// Scatter CSR + fused layer-1 scalar aggregation
__global__ void k_scatter_v4(const int* __restrict__ src, const int* __restrict__ dst, int e4) {
    int i = blockIdx.x * blockDim.x + threadIdx.x;
    if (i < e4) {
        int4 d = ((const int4*)dst)[i];
        int4 s = ((const int4*)src)[i];
        g_csr[atomicAdd(&g_cursor[d.x], 1)] = s.x;
        g_csr[atomicAdd(&g_cursor[d.y], 1)] = s.y;
        g_csr[atomicAdd(&g_cursor[d.z], 1)] = s.z;
        g_csr[atomicAdd(&g_cursor[d.w], 1)] = s.w;
        atomicAdd(&g_agg[d.x], __ldg(&g_xs[s.x]));
        atomicAdd(&g_agg[d.y], __ldg(&g_xs[s.y]));
        atomicAdd(&g_agg[d.z], __ldg(&g_xs[s.z]));
        atomicAdd(&g_agg[d.w], __ldg(&g_xs[s.w]));
    }
}
__global__ void k_scatter_s(const int* __restrict__ src, const int* __restrict__ dst, int e) {
    int i = blockIdx.x * blockDim.x + threadIdx.x;
    if (i < e) {
        int d = dst[i], s = src[i];
        g_csr[atomicAdd(&g_cursor[d], 1)] = s;
        atomicAdd(&g_agg[d], __ldg(&g_xs[s]));
    }
}

// ---------------- Layer 1 (rank-1, no gather) + transform by W2 ----------------

__global__ void __launch_bounds__(256) k_l1(const float* __restrict__ W1, const float* __restrict__ b1,
                                            const float* __restrict__ W2, int n) {
    int tid  = threadIdx.x;
    int lane = tid & 31;
    int wg   = (blockIdx.x * blockDim.x + tid) >> 5;
    int nw   = (gridDim.x * blockDim.x) >> 5;
    float wc[H];
#pragma unroll
    for (int k = 0; k < H; k++) wc[k] = __ldg(&W2[k * H + lane]);
    float w1  = __ldg(&W1[lane]);
    float bb1 = __ldg(&b1[lane]);
    for (int i = wg; i < n; i += nw) {
        float dinv = g_dinv[i];
        float S = g_agg[i] + g_xs[i];
        if (lane == 0) g_agg[i] = 0.f;            // self-clean
        float x1 = fmaxf(dinv * S * w1 + bb1, 0.f);
        float acc = 0.f;
#pragma unroll
        for (int k = 0; k < H; k++)
            acc += __shfl_sync(0xffffffffu, x1, k) * wc[k];
        g_hsA[i * H + lane] = acc * dinv;
    }
}

// ---------------- Pipelined quad-edge float4 gather ----------------
// lane = 8*g + q (g = edge subgroup 0..3, q = feature quad 0..7).
// csr indices for block k+1 are prefetched while block k's rows load.
__device__ __forceinline__ float quad_gather(const float* __restrict__ hs,
                                             float* __restrict__ xrow,
                                             int i, int st, int en, int lane) {
    int q = lane & 7, g = lane >> 3;
    float4 a = make_float4(0.f, 0.f, 0.f, 0.f);
    int nfull = (en - st) >> 5;
    int e = st;
    int idx = 0;
    if (st + lane < en) idx = __ldg(&g_csr[st + lane]);
    for (int blk = 0; blk < nfull; blk++) {
        int nidx = 0;
        int pe = e + 32 + lane;
        if (pe < en) nidx = __ldg(&g_csr[pe]);        // prefetch next block / remainder
#pragma unroll
        for (int t = 0; t < 8; t++) {
            int j = __shfl_sync(0xffffffffu, idx, t * 4 + g);
            const float4 v = *reinterpret_cast<const float4*>(&hs[j * H + q * 4]);
            a.x += v.x; a.y += v.y; a.z += v.z; a.w += v.w;
        }
        idx = nidx;
        e += 32;
    }
    int m = en - e;
    if (m > 0) {
        int nt = (m + 3) >> 2;
        for (int t = 0; t < nt; t++) {
            int ei = t * 4 + g;
            int j = __shfl_sync(0xffffffffu, idx, ei & 31);
            if (ei < m) {
                const float4 v = *reinterpret_cast<const float4*>(&hs[j * H + q * 4]);
                a.x += v.x; a.y += v.y; a.z += v.z; a.w += v.w;
            }
        }
    }
#pragma unroll
    for (int o = 8; o <= 16; o <<= 1) {
        a.x += __shfl_xor_sync(0xffffffffu, a.x, o);
        a.y += __shfl_xor_sync(0xffffffffu, a.y, o);
        a.z += __shfl_xor_sync(0xffffffffu, a.z, o);
        a.w += __shfl_xor_sync(0xffffffffu, a.w, o);
    }
    const float4 sv = *reinterpret_cast<const float4*>(&hs[i * H + q * 4]);
    a.x += sv.x; a.y += sv.y; a.z += sv.z; a.w += sv.w;
    if (g == 0) *reinterpret_cast<float4*>(&xrow[q * 4]) = a;
    __syncwarp();
    float r = xrow[lane];
    __syncwarp();
    return r;
}

// ---------------- Layer 2 gather + transform by W3 ----------------

__global__ void __launch_bounds__(256) k_g2(const float* __restrict__ b2, const float* __restrict__ W3, int n) {
    __shared__ float Xr[8][H];
    int tid  = threadIdx.x;
    int lane = tid & 31;
    int wg   = (blockIdx.x * blockDim.x + tid) >> 5;
    int nw   = (gridDim.x * blockDim.x) >> 5;
    float wc[H];
#pragma unroll
    for (int k = 0; k < H; k++) wc[k] = __ldg(&W3[k * H + lane]);
    float bb2 = __ldg(&b2[lane]);
    float* xr = Xr[tid >> 5];
    if (wg >= n) return;
    int st = g_rowstart[wg], en = g_rowstart[wg + 1];
    float dinv = g_dinv[wg];
    for (int i = wg; i < n; i += nw) {
        int inext = i + nw;
        int stn = 0, enn = 0; float dinvn = 0.f;
        if (inext < n) {                              // prefetch next node's metadata
            stn = __ldg(&g_rowstart[inext]);
            enn = __ldg(&g_rowstart[inext + 1]);
            dinvn = __ldg(&g_dinv[inext]);
        }
        float s = quad_gather(g_hsA, xr, i, st, en, lane);
        float x2 = fmaxf(s * dinv + bb2, 0.f);
        float acc = 0.f;
#pragma unroll
        for (int k = 0; k < H; k++)
            acc += __shfl_sync(0xffffffffu, x2, k) * wc[k];
        g_hsB[i * H + lane] = acc * dinv;
        st = stn; en = enn; dinv = dinvn;
    }
}

// ---------------- Layer 3 gather + theta head + pooling ----------------

__global__ void __launch_bounds__(256) k_g3(const float* __restrict__ b3, const int* __restrict__ batch,
                                            const float* __restrict__ Wt1, const float* __restrict__ bt1,
                                            const float* __restrict__ Wt2, const float* __restrict__ bt2,
                                            float* __restrict__ out, int n) {
    __shared__ float Xr[8][H];
    int tid  = threadIdx.x;
    int lane = tid & 31;
    int wg   = (blockIdx.x * blockDim.x + tid) >> 5;
    int nw   = (gridDim.x * blockDim.x) >> 5;
    float wc[H];
#pragma unroll
    for (int k = 0; k < H; k++) wc[k] = __ldg(&Wt1[k * H + lane]);
    float bb3  = __ldg(&b3[lane]);
    float bt1l = __ldg(&bt1[lane]);
    float wt2l = __ldg(&Wt2[lane]);
    float bt2s = __ldg(&bt2[0]);
    float* xr = Xr[tid >> 5];
    if (wg >= n) return;
    int st = g_rowstart[wg], en = g_rowstart[wg + 1];
    float dinv = g_dinv[wg];
    for (int i = wg; i < n; i += nw) {
        int inext = i + nw;
        int stn = 0, enn = 0; float dinvn = 0.f;
        if (inext < n) {
            stn = __ldg(&g_rowstart[inext]);
            enn = __ldg(&g_rowstart[inext + 1]);
            dinvn = __ldg(&g_dinv[inext]);
        }
        float s = quad_gather(g_hsB, xr, i, st, en, lane);
        float h = fmaxf(s * dinv + bb3, 0.f);
        float acc = bt1l;
#pragma unroll
        for (int k = 0; k < H; k++)
            acc += __shfl_sync(0xffffffffu, h, k) * wc[k];
        float p = fmaxf(acc, 0.f) * wt2l;
#pragma unroll
        for (int o = 16; o > 0; o >>= 1) p += __shfl_xor_sync(0xffffffffu, p, o);
        int g = batch[i];
        atomicAdd(&g_gsum[g * H + lane], h);
        if (lane == 0) {
            atomicAdd(&g_gcnt[g], 1.f);
            out[i] = 3.14159265358979323846f / (1.f + expf(-(p + bt2s)));
        }
        st = stn; en = enn; dinv = dinvn;
    }
}

// ---------------- Per-graph MLP head (+ self-clean) ----------------

__global__ void k_graph(const float* __restrict__ Wg1, const float* __restrict__ bg1,
                        const float* __restrict__ Wg2, const float* __restrict__ bg2,
                        float* __restrict__ out, int n, int g) {
    int wid = (blockIdx.x * blockDim.x + threadIdx.x) >> 5;
    int lane = threadIdx.x & 31;
    if (wid >= g) return;
    float cnt = g_gcnt[wid];
    float ge = g_gsum[wid * H + lane] / fmaxf(cnt, 1.f);
    g_gsum[wid * H + lane] = 0.f;                  // self-clean
    if (lane == 0) g_gcnt[wid] = 0.f;
    float acc = __ldg(&bg1[lane]);
#pragma unroll
    for (int k = 0; k < H; k++)
        acc += __shfl_sync(0xffffffffu, ge, k) * __ldg(&Wg1[k * H + lane]);
    float t = fmaxf(acc, 0.f);
    float p0 = t * __ldg(&Wg2[lane * 2 + 0]);
    float p1 = t * __ldg(&Wg2[lane * 2 + 1]);
#pragma unroll
    for (int o = 16; o > 0; o >>= 1) {
        p0 += __shfl_xor_sync(0xffffffffu, p0, o);
        p1 += __shfl_xor_sync(0xffffffffu, p1, o);
    }
    if (lane == 0) {
        const float TWO_PI = 6.28318530717958647692f;
        out[n + wid * 2 + 0] = TWO_PI / (1.f + expf(-(p0 + __ldg(&bg2[0]))));
        out[n + wid * 2 + 1] = TWO_PI / (1.f + expf(-(p1 + __ldg(&bg2[1]))));
    }
}

extern "C" void kernel_launch(void* const* d_in, const int* in_sizes, int n_in,
                              void* d_out, int out_size) {
    const float* x   = (const float*)d_in[0];
    const int*   ei  = (const int*)d_in[1];
    const int*   bat = (const int*)d_in[2];
    const float* W1  = (const float*)d_in[3];
    const float* b1  = (const float*)d_in[4];
    const float* W2  = (const float*)d_in[5];
    const float* b2  = (const float*)d_in[6];
    const float* W3  = (const float*)d_in[7];
    const float* b3  = (const float*)d_in[8];
    const float* Wt1 = (const float*)d_in[9];
    const float* bt1 = (const float*)d_in[10];
    const float* Wt2 = (const float*)d_in[11];
    const float* bt2 = (const float*)d_in[12];
    const float* Wg1 = (const float*)d_in[13];
    const float* bg1 = (const float*)d_in[14];
    const float* Wg2 = (const float*)d_in[15];
    const float* bg2 = (const float*)d_in[16];
    float* out = (float*)d_out;

    int N = in_sizes[0];
    int E = in_sizes[1] / 2;
    int G = (out_size - N) / 2;

    const int* src = ei;
    const int* dst = ei + E;

    const int TB = 256;
    int CH = (N + NCHUNK - 1) / NCHUNK;   // must be <= 1024 (N <= 131072)
    int nb_g = (G * 32 + TB - 1) / TB;

    bool vec4 = ((E & 3) == 0) &&
                ((((unsigned long long)src) & 15ull) == 0) &&
                ((((unsigned long long)dst) & 15ull) == 0);

    if (vec4) {
        int e4 = E / 4;
        int nb = (e4 + TB - 1) / TB;
        k_count_v4<<<nb, TB>>>(dst, e4);
        k_chunksum<<<NCHUNK, TB>>>(N, CH);
        k_chunkscan<<<NCHUNK, 1024>>>(x, N, CH);
        k_scatter_v4<<<nb, TB>>>(src, dst, e4);   // launch index 3 -> profiled
    } else {
        int nb = (E + TB - 1) / TB;
        k_count_s<<<nb, TB>>>(dst, E);
        k_chunksum<<<NCHUNK, TB>>>(N, CH);
        k_chunkscan<<<NCHUNK, 1024>>>(x, N, CH);
        k_scatter_s<<<nb, TB>>>(src, dst, E);
    }

    k_l1<<<592, TB>>>(W1, b1, W2, N);
    k_g2<<<1184, TB>>>(b2, W3, N);
    k_g3<<<1184, TB>>>(b3, bat, Wt1, bt1, Wt2, bt2, out, N);
    k_graph<<<nb_g, TB>>>(Wg1, bg1, Wg2, bg2, out, N, G);
}